// round 3
// baseline (speedup 1.0000x reference)
#include <cuda_runtime.h>
#include <cstddef>

#define NN 50000
#define FD 128
#define NE 600000

typedef unsigned long long ull;

// ---------------- device scratch (no allocation allowed) ----------------
__device__ float g_h1[NN * FD];
__device__ float g_h2[NN * FD];
__device__ float g_hn[NN * FD];       // mean-aggregated neighbor feats
__device__ float g_invdeg[NN];
__device__ int   g_count[NN];
__device__ int   g_rowstart[NN];
__device__ int   g_cursor[NN];
__device__ int   g_eidx[NE];          // CSR: src ids grouped by dst
__device__ float g_w2s[128 * 128];    // layer-2 weights padded to 128 cols
__device__ float g_w2n[128 * 128];
__device__ float g_b2[128];

// ---------------- packed f32x2 helpers ----------------
__device__ __forceinline__ ull pack2(float x, float y) {
    ull r; asm("mov.b64 %0, {%1,%2};" : "=l"(r) : "f"(x), "f"(y)); return r;
}
__device__ __forceinline__ void unpack2(ull v, float& x, float& y) {
    asm("mov.b64 {%0,%1}, %2;" : "=f"(x), "=f"(y) : "l"(v));
}
__device__ __forceinline__ void fma2(ull& d, ull a, ull b) {
    asm("fma.rn.f32x2 %0, %1, %2, %0;" : "+l"(d) : "l"(a), "l"(b));
}

// ---------------- CSR build ----------------

__global__ void zero_counts_kernel() {
    int i = blockIdx.x * blockDim.x + threadIdx.x;
    if (i < NN) g_count[i] = 0;
}

__global__ void hist_kernel(const int* __restrict__ dst) {
    int e = blockIdx.x * blockDim.x + threadIdx.x;
    if (e < NE) atomicAdd(&g_count[dst[e]], 1);
}

// single block, 1024 threads: chunked exclusive scan + invdeg + zero cursor
#define SCAN_T 1024
__global__ void __launch_bounds__(SCAN_T) scan_kernel() {
    __shared__ int s[SCAN_T];
    int tid = threadIdx.x;
    const int CH = (NN + SCAN_T - 1) / SCAN_T;   // 49
    int t0 = tid * CH;
    int t1 = t0 + CH; if (t1 > NN) t1 = NN;
    int sum = 0;
    for (int i = t0; i < t1; ++i) sum += g_count[i];
    s[tid] = sum;
    __syncthreads();
    for (int off = 1; off < SCAN_T; off <<= 1) {
        int v = (tid >= off) ? s[tid - off] : 0;
        __syncthreads();
        s[tid] += v;
        __syncthreads();
    }
    int run = s[tid] - sum;                       // exclusive prefix
    for (int i = t0; i < t1; ++i) {
        int c = g_count[i];
        g_rowstart[i] = run; run += c;
        g_invdeg[i] = 1.0f / fmaxf((float)c, 1.0f);
        g_cursor[i] = 0;
    }
}

__global__ void fill_kernel(const int* __restrict__ src, const int* __restrict__ dst) {
    int e = blockIdx.x * blockDim.x + threadIdx.x;
    if (e < NE) {
        int d = dst[e];
        int p = atomicAdd(&g_cursor[d], 1);
        g_eidx[g_rowstart[d] + p] = src[e];
    }
}

__global__ void pad_w2_kernel(const float* __restrict__ Ws2,
                              const float* __restrict__ Wn2,
                              const float* __restrict__ b2) {
    int i = blockIdx.x * blockDim.x + threadIdx.x;   // 0..16383
    if (i < 128 * 128) {
        int k = i >> 7, j = i & 127;
        g_w2s[i] = (j < 47) ? Ws2[k * 47 + j] : 0.f;
        g_w2n[i] = (j < 47) ? Wn2[k * 47 + j] : 0.f;
        if (i < 128) g_b2[i] = (i < 47) ? b2[i] : 0.f;
    }
}

// ---------------- gather: mean neighbor aggregation, no atomics ----------------
// One warp per node; each lane owns 4 contiguous feats (float4).

__global__ void __launch_bounds__(256) gather_kernel(const float* __restrict__ h) {
    int node = (blockIdx.x * blockDim.x + threadIdx.x) >> 5;
    int lane = threadIdx.x & 31;
    if (node >= NN) return;
    int start = g_rowstart[node];
    int len   = g_count[node];
    float4 acc = make_float4(0.f, 0.f, 0.f, 0.f);
    int e = 0;
    for (; e + 4 <= len; e += 4) {
        int s0 = g_eidx[start + e];
        int s1 = g_eidx[start + e + 1];
        int s2 = g_eidx[start + e + 2];
        int s3 = g_eidx[start + e + 3];
        float4 v0 = *(const float4*)(h + (size_t)s0 * FD + lane * 4);
        float4 v1 = *(const float4*)(h + (size_t)s1 * FD + lane * 4);
        float4 v2 = *(const float4*)(h + (size_t)s2 * FD + lane * 4);
        float4 v3 = *(const float4*)(h + (size_t)s3 * FD + lane * 4);
        acc.x += v0.x + v1.x + v2.x + v3.x;
        acc.y += v0.y + v1.y + v2.y + v3.y;
        acc.z += v0.z + v1.z + v2.z + v3.z;
        acc.w += v0.w + v1.w + v2.w + v3.w;
    }
    for (; e < len; ++e) {
        int s0 = g_eidx[start + e];
        float4 v0 = *(const float4*)(h + (size_t)s0 * FD + lane * 4);
        acc.x += v0.x; acc.y += v0.y; acc.z += v0.z; acc.w += v0.w;
    }
    float inv = g_invdeg[node];
    acc.x *= inv; acc.y *= inv; acc.z *= inv; acc.w *= inv;
    *(float4*)(g_hn + (size_t)node * FD + lane * 4) = acc;
}

// ---------------- fused dual-GEMM + bias + relu (packed f32x2) ----------------
// out[row,j] = act( h[row,:]@Ws[:,j] + hn[row,:]@Wn[:,j] + b[j] )
// Block: 64 rows x 128 cols, 256 threads. Thread: 8 rows (4 packed pairs) x 4 cols.
// Weights stored col-splatted packed (w,w); activations k-major so adjacent rows
// form natural f32x2 pairs.

#define SH_STRIDE 68   // 68*4B = 272B, 16B aligned rows

__global__ void __launch_bounds__(256) gemm_kernel(
    const float* __restrict__ h,
    const float* __restrict__ Ws,
    const float* __restrict__ Wn,
    const float* __restrict__ bias,
    float* __restrict__ out,
    int fout, int do_relu)
{
    extern __shared__ char smem_raw[];
    ull*   s_wsp = (ull*)smem_raw;            // [32][128] packed
    ull*   s_wnp = s_wsp + 32 * 128;          // [32][128] packed
    float* s_h   = (float*)(s_wnp + 32 * 128); // [32][SH_STRIDE] k-major
    float* s_hn  = s_h + 32 * SH_STRIDE;

    const int tid = threadIdx.x;
    const int tj = tid & 31;      // col group: cols 4*tj..4*tj+3
    const int tr = tid >> 5;      // row group: rows 8*tr..8*tr+7
    const int row0 = blockIdx.x * 64;

    ull acc[4][4];
#pragma unroll
    for (int c = 0; c < 4; ++c) {
        float bv = __ldg(bias + tj * 4 + c);
        ull p = pack2(bv, bv);
#pragma unroll
        for (int rp = 0; rp < 4; ++rp) acc[rp][c] = p;
    }

    for (int kt = 0; kt < 4; ++kt) {
        // load + splat weights: 32 k x 128 j per matrix
#pragma unroll
        for (int i = 0; i < 4; ++i) {
            int idx = tid + i * 256;
            int k = idx >> 5;
            int jq = idx & 31;
            float4 w = *(const float4*)(Ws + (size_t)(kt * 32 + k) * 128 + jq * 4);
            ull* d = &s_wsp[k * 128 + jq * 4];
            d[0] = pack2(w.x, w.x); d[1] = pack2(w.y, w.y);
            d[2] = pack2(w.z, w.z); d[3] = pack2(w.w, w.w);
            float4 w2 = *(const float4*)(Wn + (size_t)(kt * 32 + k) * 128 + jq * 4);
            ull* d2 = &s_wnp[k * 128 + jq * 4];
            d2[0] = pack2(w2.x, w2.x); d2[1] = pack2(w2.y, w2.y);
            d2[2] = pack2(w2.z, w2.z); d2[3] = pack2(w2.w, w2.w);
        }
        // load activations transposed: 64 rows x 32 k
#pragma unroll
        for (int i = 0; i < 2; ++i) {
            int idx = tid + i * 256;
            int r  = idx >> 3;     // 0..63
            int kq = idx & 7;
            int row = row0 + r;
            float4 a = make_float4(0.f, 0.f, 0.f, 0.f);
            float4 n = make_float4(0.f, 0.f, 0.f, 0.f);
            if (row < NN) {
                a = *(const float4*)(h    + (size_t)row * FD + kt * 32 + kq * 4);
                n = *(const float4*)(g_hn + (size_t)row * FD + kt * 32 + kq * 4);
            }
            s_h [(kq * 4 + 0) * SH_STRIDE + r] = a.x;
            s_h [(kq * 4 + 1) * SH_STRIDE + r] = a.y;
            s_h [(kq * 4 + 2) * SH_STRIDE + r] = a.z;
            s_h [(kq * 4 + 3) * SH_STRIDE + r] = a.w;
            s_hn[(kq * 4 + 0) * SH_STRIDE + r] = n.x;
            s_hn[(kq * 4 + 1) * SH_STRIDE + r] = n.y;
            s_hn[(kq * 4 + 2) * SH_STRIDE + r] = n.z;
            s_hn[(kq * 4 + 3) * SH_STRIDE + r] = n.w;
        }
        __syncthreads();

#pragma unroll
        for (int k = 0; k < 32; ++k) {
            ulonglong2 wA = *(const ulonglong2*)&s_wsp[k * 128 + tj * 4];
            ulonglong2 wB = *(const ulonglong2*)&s_wsp[k * 128 + tj * 4 + 2];
            ulonglong2 nA = *(const ulonglong2*)&s_wnp[k * 128 + tj * 4];
            ulonglong2 nB = *(const ulonglong2*)&s_wnp[k * 128 + tj * 4 + 2];
            const ull* ap = (const ull*)&s_h [k * SH_STRIDE + tr * 8];
            const ull* bp = (const ull*)&s_hn[k * SH_STRIDE + tr * 8];
            ulonglong2 aA = *(const ulonglong2*)ap;       // row pairs 0,1
            ulonglong2 aB = *(const ulonglong2*)(ap + 2); // row pairs 2,3
            ulonglong2 bA = *(const ulonglong2*)bp;
            ulonglong2 bB = *(const ulonglong2*)(bp + 2);
            ull av[4] = {aA.x, aA.y, aB.x, aB.y};
            ull bv[4] = {bA.x, bA.y, bB.x, bB.y};
            ull wv[4] = {wA.x, wA.y, wB.x, wB.y};
            ull nv[4] = {nA.x, nA.y, nB.x, nB.y};
#pragma unroll
            for (int rp = 0; rp < 4; ++rp) {
#pragma unroll
                for (int c = 0; c < 4; ++c) {
                    fma2(acc[rp][c], av[rp], wv[c]);
                    fma2(acc[rp][c], bv[rp], nv[c]);
                }
            }
        }
        __syncthreads();
    }

    // epilogue
#pragma unroll
    for (int rp = 0; rp < 4; ++rp) {
        int row_a = row0 + tr * 8 + rp * 2;
        int row_b = row_a + 1;
#pragma unroll
        for (int c = 0; c < 4; ++c) {
            float lo, hi;
            unpack2(acc[rp][c], lo, hi);
            if (do_relu) { lo = fmaxf(lo, 0.f); hi = fmaxf(hi, 0.f); }
            int j = tj * 4 + c;
            if (j < fout) {
                if (row_a < NN) out[(size_t)row_a * fout + j] = lo;
                if (row_b < NN) out[(size_t)row_b * fout + j] = hi;
            }
        }
    }
}

// ---------------- launch ----------------

extern "C" void kernel_launch(void* const* d_in, const int* in_sizes, int n_in,
                              void* d_out, int out_size) {
    const float* x   = (const float*)d_in[0];
    const int*   src = (const int*)d_in[1];
    const int*   dst = (const int*)d_in[2];
    const float* Ws0 = (const float*)d_in[3];
    const float* Wn0 = (const float*)d_in[4];
    const float* b0  = (const float*)d_in[5];
    const float* Ws1 = (const float*)d_in[6];
    const float* Wn1 = (const float*)d_in[7];
    const float* b1  = (const float*)d_in[8];
    const float* Ws2 = (const float*)d_in[9];
    const float* Wn2 = (const float*)d_in[10];
    const float* b2  = (const float*)d_in[11];
    float* out = (float*)d_out;

    float *h1, *h2, *w2s, *w2n, *pb2;
    cudaGetSymbolAddress((void**)&h1, g_h1);
    cudaGetSymbolAddress((void**)&h2, g_h2);
    cudaGetSymbolAddress((void**)&w2s, g_w2s);
    cudaGetSymbolAddress((void**)&w2n, g_w2n);
    cudaGetSymbolAddress((void**)&pb2, g_b2);

    const int smem_bytes = 2 * 32 * 128 * 8 + 2 * 32 * SH_STRIDE * 4;  // 82944
    cudaFuncSetAttribute(gemm_kernel, cudaFuncAttributeMaxDynamicSharedMemorySize, smem_bytes);

    const int ZB = 256;
    const int node_grid   = (NN + ZB - 1) / ZB;
    const int edge_grid   = (NE + ZB - 1) / ZB;
    const int gather_grid = (NN * 32 + ZB - 1) / ZB;
    const int gemm_grid   = (NN + 63) / 64;

    // CSR build (per-call, deterministic work)
    zero_counts_kernel<<<node_grid, ZB>>>();
    hist_kernel<<<edge_grid, ZB>>>(dst);
    scan_kernel<<<1, SCAN_T>>>();
    fill_kernel<<<edge_grid, ZB>>>(src, dst);
    pad_w2_kernel<<<64, ZB>>>(Ws2, Wn2, b2);

    // layer 0: x -> h1 (relu)
    gather_kernel<<<gather_grid, ZB>>>(x);
    gemm_kernel<<<gemm_grid, 256, smem_bytes>>>(x, Ws0, Wn0, b0, h1, 128, 1);

    // layer 1: h1 -> h2 (relu)
    gather_kernel<<<gather_grid, ZB>>>(h1);
    gemm_kernel<<<gemm_grid, 256, smem_bytes>>>(h1, Ws1, Wn1, b1, h2, 128, 1);

    // layer 2: h2 -> out (no relu, fout=47 via padded weights)
    gather_kernel<<<gather_grid, ZB>>>(h2);
    gemm_kernel<<<gemm_grid, 256, smem_bytes>>>(h2, w2s, w2n, pb2, out, 47, 0);
}

// round 9
// speedup vs baseline: 1.0465x; 1.0465x over previous
#include <cuda_runtime.h>
#include <cuda_bf16.h>
#include <cstdint>
#include <cstddef>

#define NN 50000
#define FD 128
#define NE 600000
#define MTILE 64
#define NTILES 782   // ceil(50000/64)
#define KPAD 136     // A smem row stride in bf16 units (272B: conflict-free ldmatrix)

typedef unsigned int uint32;

// ---------------- device scratch (no allocation allowed) ----------------
__device__ float g_h1[NN * FD];
__device__ float g_h2[NN * FD];
__device__ float g_hn[NN * FD];        // mean-aggregated neighbor feats
__device__ float g_invdeg[NN];
__device__ int   g_count[NN];
__device__ int   g_rowstart[NN];
__device__ int   g_cursor[NN];
__device__ int   g_eidx[NE];           // CSR: src ids grouped by dst
__device__ unsigned short g_wthi[3][128 * 256];  // W^T bf16 hi: [n][k], k = [self | neigh]
__device__ unsigned short g_wtlo[3][128 * 256];  // W^T bf16 lo
__device__ float g_biasp[3][128];

// ---------------- PTX helpers (base-target only; NO tcgen05) ----------------
__device__ __forceinline__ uint32 smem_u32(const void* p) {
    uint32 a;
    asm("{ .reg .u64 t; cvta.to.shared.u64 t, %1; cvt.u32.u64 %0, t; }" : "=r"(a) : "l"(p));
    return a;
}

#define LDMATRIX_X4(r0, r1, r2, r3, addr) \
    asm volatile("ldmatrix.sync.aligned.m8n8.x4.shared.b16 {%0,%1,%2,%3}, [%4];" \
        : "=r"(r0), "=r"(r1), "=r"(r2), "=r"(r3) : "r"(addr))

#define MMA_BF16(d, a, b0, b1) \
    asm volatile("mma.sync.aligned.m16n8k16.row.col.f32.bf16.bf16.f32 " \
        "{%0,%1,%2,%3}, {%4,%5,%6,%7}, {%8,%9}, {%0,%1,%2,%3};" \
        : "+f"((d)[0]), "+f"((d)[1]), "+f"((d)[2]), "+f"((d)[3]) \
        : "r"((a)[0]), "r"((a)[1]), "r"((a)[2]), "r"((a)[3]), "r"(b0), "r"(b1))

// bf16 hi/lo split of a float pair -> (hi bf16x2, lo bf16x2); low half = first elem
__device__ __forceinline__ uint2 split_pair(float v0, float v1) {
    uint32 hp, lp;
    asm("cvt.rn.bf16x2.f32 %0, %1, %2;" : "=r"(hp) : "f"(v1), "f"(v0));
    float h0 = __uint_as_float(hp << 16);
    float h1 = __uint_as_float(hp & 0xFFFF0000u);
    float r0 = v0 - h0, r1 = v1 - h1;
    asm("cvt.rn.bf16x2.f32 %0, %1, %2;" : "=r"(lp) : "f"(r1), "f"(r0));
    return make_uint2(hp, lp);
}

// ---------------- CSR build ----------------

__global__ void zero_counts_kernel() {
    int i = blockIdx.x * blockDim.x + threadIdx.x;
    if (i < NN) g_count[i] = 0;
}

__global__ void hist_kernel(const int* __restrict__ dst) {
    int e = blockIdx.x * blockDim.x + threadIdx.x;
    if (e < NE) atomicAdd(&g_count[dst[e]], 1);
}

#define SCAN_T 1024
__global__ void __launch_bounds__(SCAN_T) scan_kernel() {
    __shared__ int s[SCAN_T];
    int tid = threadIdx.x;
    const int CH = (NN + SCAN_T - 1) / SCAN_T;
    int t0 = tid * CH;
    int t1 = t0 + CH; if (t1 > NN) t1 = NN;
    int sum = 0;
    for (int i = t0; i < t1; ++i) sum += g_count[i];
    s[tid] = sum;
    __syncthreads();
    for (int off = 1; off < SCAN_T; off <<= 1) {
        int v = (tid >= off) ? s[tid - off] : 0;
        __syncthreads();
        s[tid] += v;
        __syncthreads();
    }
    int run = s[tid] - sum;
    for (int i = t0; i < t1; ++i) {
        int c = g_count[i];
        g_rowstart[i] = run; run += c;
        g_invdeg[i] = 1.0f / fmaxf((float)c, 1.0f);
        g_cursor[i] = 0;
    }
}

__global__ void fill_kernel(const int* __restrict__ src, const int* __restrict__ dst) {
    int e = blockIdx.x * blockDim.x + threadIdx.x;
    if (e < NE) {
        int d = dst[e];
        int p = atomicAdd(&g_cursor[d], 1);
        g_eidx[g_rowstart[d] + p] = src[e];
    }
}

// ---------------- weight prep: transpose + K-concat + bf16 split + bias pad ----------------

__global__ void prep_w_kernel(const float* __restrict__ Ws0, const float* __restrict__ Wn0, const float* __restrict__ b0,
                              const float* __restrict__ Ws1, const float* __restrict__ Wn1, const float* __restrict__ b1,
                              const float* __restrict__ Ws2, const float* __restrict__ Wn2, const float* __restrict__ b2) {
    int i = blockIdx.x * blockDim.x + threadIdx.x;    // 0 .. 3*128*256-1
    if (i < 3 * 128 * 256) {
        int l = i / (128 * 256);
        int rem = i - l * 128 * 256;
        int n = rem >> 8;        // 0..127 (output col)
        int k = rem & 255;       // 0..255 (concat K)
        float v = 0.f;
        if (l == 0) {
            v = (k < 128) ? Ws0[k * 128 + n] : Wn0[(k - 128) * 128 + n];
        } else if (l == 1) {
            v = (k < 128) ? Ws1[k * 128 + n] : Wn1[(k - 128) * 128 + n];
        } else if (n < 47) {
            v = (k < 128) ? Ws2[k * 47 + n] : Wn2[(k - 128) * 47 + n];
        }
        __nv_bfloat16 hb = __float2bfloat16_rn(v);
        float hf = __bfloat162float(hb);
        __nv_bfloat16 lb = __float2bfloat16_rn(v - hf);
        g_wthi[l][rem] = __bfloat16_as_ushort(hb);
        g_wtlo[l][rem] = __bfloat16_as_ushort(lb);
    }
    if (i < 3 * 128) {
        int l = i >> 7, j = i & 127;
        float bv = 0.f;
        if (l == 0) bv = b0[j];
        else if (l == 1) bv = b1[j];
        else if (j < 47) bv = b2[j];
        g_biasp[l][j] = bv;
    }
}

// ---------------- gather: mean neighbor aggregation (CSR, no atomics) ----------------

__global__ void __launch_bounds__(256) gather_kernel(const float* __restrict__ h) {
    int node = (blockIdx.x * blockDim.x + threadIdx.x) >> 5;
    int lane = threadIdx.x & 31;
    if (node >= NN) return;
    int start = g_rowstart[node];
    int len   = g_count[node];
    float4 acc = make_float4(0.f, 0.f, 0.f, 0.f);
    int e = 0;
    for (; e + 4 <= len; e += 4) {
        int s0 = g_eidx[start + e];
        int s1 = g_eidx[start + e + 1];
        int s2 = g_eidx[start + e + 2];
        int s3 = g_eidx[start + e + 3];
        float4 v0 = *(const float4*)(h + (size_t)s0 * FD + lane * 4);
        float4 v1 = *(const float4*)(h + (size_t)s1 * FD + lane * 4);
        float4 v2 = *(const float4*)(h + (size_t)s2 * FD + lane * 4);
        float4 v3 = *(const float4*)(h + (size_t)s3 * FD + lane * 4);
        acc.x += v0.x + v1.x + v2.x + v3.x;
        acc.y += v0.y + v1.y + v2.y + v3.y;
        acc.z += v0.z + v1.z + v2.z + v3.z;
        acc.w += v0.w + v1.w + v2.w + v3.w;
    }
    for (; e < len; ++e) {
        int s0 = g_eidx[start + e];
        float4 v0 = *(const float4*)(h + (size_t)s0 * FD + lane * 4);
        acc.x += v0.x; acc.y += v0.y; acc.z += v0.z; acc.w += v0.w;
    }
    float inv = g_invdeg[node];
    acc.x *= inv; acc.y *= inv; acc.z *= inv; acc.w *= inv;
    *(float4*)(g_hn + (size_t)node * FD + lane * 4) = acc;
}

// ---------------- HMMA bf16-split fused dual GEMM ----------------
// out[50000, fout] = act( [h | hn] @ Wt^T + bias ), 64-row tiles, K=256 concat.
// Per chunk: A fp32 -> bf16 hi/lo in SMEM; B hi/lo fragments loaded directly
// from prepped gmem (L2-resident). 3 passes: ahi*bhi + alo*bhi + ahi*blo.
// Block: 8 warps, 2(M) x 4(N); warp tile 32x32; mma m16n8k16.
// smem = 2 * 64 * KPAD * 2 bytes = 34816 (< 48KB, no opt-in).

__global__ void __launch_bounds__(256)
gemm_kernel(const float* __restrict__ h, int layer,
            float* __restrict__ out, int fout, int do_relu)
{
    extern __shared__ unsigned short smem[];
    unsigned short* s_ahi = smem;                 // [64][KPAD]
    unsigned short* s_alo = smem + MTILE * KPAD;

    const int tid = threadIdx.x;
    const int wid = tid >> 5;
    const int lane = tid & 31;
    const int warp_m = wid & 1;     // rows 32*warp_m .. +31
    const int warp_n = wid >> 1;    // cols 32*warp_n .. +31
    const int row0 = blockIdx.x * MTILE;

    const uint32 sa_hi = smem_u32(s_ahi);
    const uint32 sa_lo = smem_u32(s_alo);

    // ldmatrix lane addressing for 16x16 A tiles
    const int lm_l = lane & 7;
    const int lm_g = lane >> 3;
    const int lm_row = ((lm_g & 1) << 3) + lm_l;   // +0/+8 within tile
    const int lm_kof = (lm_g & 2) << 2;            // 0 or 8

    float acc[2][4][4];
#pragma unroll
    for (int mt = 0; mt < 2; ++mt)
#pragma unroll
        for (int nt = 0; nt < 4; ++nt)
#pragma unroll
            for (int c = 0; c < 4; ++c) acc[mt][nt][c] = 0.f;

    for (int chunk = 0; chunk < 2; ++chunk) {
        const float* A = (chunk == 0) ? h : g_hn;
        // --- A fill: 64 rows x 128 k fp32 -> bf16 hi/lo SMEM ---
#pragma unroll
        for (int it = 0; it < 8; ++it) {
            int id = tid + it * 256;       // 0..2047
            int r = id >> 5;               // row in tile (0..63)
            int q = id & 31;               // k-quad
            int row = row0 + r;
            float4 v = make_float4(0.f, 0.f, 0.f, 0.f);
            if (row < NN) v = *(const float4*)(A + (size_t)row * FD + q * 4);
            uint2 p01 = split_pair(v.x, v.y);
            uint2 p23 = split_pair(v.z, v.w);
            uint32* ph = (uint32*)(s_ahi + r * KPAD + q * 4);
            ph[0] = p01.x; ph[1] = p23.x;
            uint32* pl = (uint32*)(s_alo + r * KPAD + q * 4);
            pl[0] = p01.y; pl[1] = p23.y;
        }
        __syncthreads();

        const unsigned short* __restrict__ Wh = g_wthi[layer] + chunk * 128;
        const unsigned short* __restrict__ Wl = g_wtlo[layer] + chunk * 128;
        const int bn = warp_n * 32 + (lane >> 2);   // n for this thread (per ntile: +8*nt)
        const int bq = (lane & 3) * 2;              // k pair offset within k-step

#pragma unroll
        for (int ks = 0; ks < 8; ++ks) {
            const int k0 = ks * 16;
            // A fragments (hi & lo) for both 16-row tiles
            uint32 ah[2][4], al[2][4];
#pragma unroll
            for (int mt = 0; mt < 2; ++mt) {
                int m = warp_m * 32 + mt * 16 + lm_row;
                uint32 off = (uint32)((m * KPAD + k0 + lm_kof) * 2);
                LDMATRIX_X4(ah[mt][0], ah[mt][1], ah[mt][2], ah[mt][3], sa_hi + off);
                LDMATRIX_X4(al[mt][0], al[mt][1], al[mt][2], al[mt][3], sa_lo + off);
            }
#pragma unroll
            for (int nt = 0; nt < 4; ++nt) {
                const unsigned short* wh = Wh + (size_t)(bn + nt * 8) * 256 + k0 + bq;
                const unsigned short* wl = Wl + (size_t)(bn + nt * 8) * 256 + k0 + bq;
                uint32 bh0 = __ldg((const uint32*)wh);
                uint32 bh1 = __ldg((const uint32*)(wh + 8));
                uint32 bl0 = __ldg((const uint32*)wl);
                uint32 bl1 = __ldg((const uint32*)(wl + 8));
#pragma unroll
                for (int mt = 0; mt < 2; ++mt) {
                    MMA_BF16(acc[mt][nt], ah[mt], bh0, bh1);   // hi*hi
                    MMA_BF16(acc[mt][nt], al[mt], bh0, bh1);   // lo*hi
                    MMA_BF16(acc[mt][nt], ah[mt], bl0, bl1);   // hi*lo
                }
            }
        }
        __syncthreads();
    }

    // --- epilogue: bias + relu + store ---
    const float* bias = g_biasp[layer];
#pragma unroll
    for (int mt = 0; mt < 2; ++mt) {
        int r_a = row0 + warp_m * 32 + mt * 16 + (lane >> 2);
        int r_b = r_a + 8;
#pragma unroll
        for (int nt = 0; nt < 4; ++nt) {
            int j0 = warp_n * 32 + nt * 8 + (lane & 3) * 2;
            float b0v = bias[j0], b1v = bias[j0 + 1];
            float v0 = acc[mt][nt][0] + b0v;
            float v1 = acc[mt][nt][1] + b1v;
            float v2 = acc[mt][nt][2] + b0v;
            float v3 = acc[mt][nt][3] + b1v;
            if (do_relu) {
                v0 = fmaxf(v0, 0.f); v1 = fmaxf(v1, 0.f);
                v2 = fmaxf(v2, 0.f); v3 = fmaxf(v3, 0.f);
            }
            if (r_a < NN) {
                if (j0 < fout)     out[(size_t)r_a * fout + j0]     = v0;
                if (j0 + 1 < fout) out[(size_t)r_a * fout + j0 + 1] = v1;
            }
            if (r_b < NN) {
                if (j0 < fout)     out[(size_t)r_b * fout + j0]     = v2;
                if (j0 + 1 < fout) out[(size_t)r_b * fout + j0 + 1] = v3;
            }
        }
    }
}

// ---------------- launch ----------------

extern "C" void kernel_launch(void* const* d_in, const int* in_sizes, int n_in,
                              void* d_out, int out_size) {
    const float* x   = (const float*)d_in[0];
    const int*   src = (const int*)d_in[1];
    const int*   dst = (const int*)d_in[2];
    const float* Ws0 = (const float*)d_in[3];
    const float* Wn0 = (const float*)d_in[4];
    const float* b0  = (const float*)d_in[5];
    const float* Ws1 = (const float*)d_in[6];
    const float* Wn1 = (const float*)d_in[7];
    const float* b1  = (const float*)d_in[8];
    const float* Ws2 = (const float*)d_in[9];
    const float* Wn2 = (const float*)d_in[10];
    const float* b2  = (const float*)d_in[11];
    float* out = (float*)d_out;

    float *h1, *h2;
    cudaGetSymbolAddress((void**)&h1, g_h1);
    cudaGetSymbolAddress((void**)&h2, g_h2);

    const int smem_bytes = 2 * MTILE * KPAD * 2;   // 34816 < 48KB

    const int ZB = 256;
    const int node_grid   = (NN + ZB - 1) / ZB;
    const int edge_grid   = (NE + ZB - 1) / ZB;
    const int gather_grid = (NN * 32 + ZB - 1) / ZB;
    const int prep_grid   = (3 * 128 * 256 + ZB - 1) / ZB;

    // CSR build + weight prep
    zero_counts_kernel<<<node_grid, ZB>>>();
    hist_kernel<<<edge_grid, ZB>>>(dst);
    scan_kernel<<<1, SCAN_T>>>();
    fill_kernel<<<edge_grid, ZB>>>(src, dst);
    prep_w_kernel<<<prep_grid, ZB>>>(Ws0, Wn0, b0, Ws1, Wn1, b1, Ws2, Wn2, b2);

    // layer 0: x -> h1 (relu)
    gather_kernel<<<gather_grid, ZB>>>(x);
    gemm_kernel<<<NTILES, 256, smem_bytes>>>(x, 0, h1, 128, 1);

    // layer 1: h1 -> h2 (relu)
    gather_kernel<<<gather_grid, ZB>>>(h1);
    gemm_kernel<<<NTILES, 256, smem_bytes>>>(h1, 1, h2, 128, 1);

    // layer 2: h2 -> out (no relu, fout=47)
    gather_kernel<<<gather_grid, ZB>>>(h2);
    gemm_kernel<<<NTILES, 256, smem_bytes>>>(h2, 2, out, 47, 0);
}

// round 13
// speedup vs baseline: 2.2391x; 2.1397x over previous
#include <cuda_runtime.h>
#include <cuda_bf16.h>
#include <cstdint>
#include <cstddef>

#define NN 50000
#define FD 128
#define NE 600000
#define MTILE 64
#define NTILES 782   // ceil(50000/64)
#define KPAD 136     // A smem row stride in bf16 units (272B: conflict-free ldmatrix)

typedef unsigned int uint32;

// ---------------- device scratch (no allocation allowed) ----------------
__device__ float g_h1[NN * FD];
__device__ float g_h2[NN * FD];
__device__ float g_hn[NN * FD];        // mean-aggregated neighbor feats
__device__ float g_invdeg[NN];
__device__ int   g_count[NN];
__device__ int   g_rowstart[NN];
__device__ int   g_cursor[NN];
__device__ int   g_eidx[NE];           // CSR: src ids grouped by dst
// B weights in MMA-fragment order: [layer][chunk][ks][nb][lane] -> (bh0,bh1,bl0,bl1)
// layer 3, chunk 2, ks 8, nb 16 (8-n blocks), lane 32
__device__ uint4 g_wfrag[3 * 2 * 8 * 16 * 32];
__device__ float g_biasp[3][128];

// ---------------- PTX helpers (base-target only; NO tcgen05) ----------------
__device__ __forceinline__ uint32 smem_u32(const void* p) {
    uint32 a;
    asm("{ .reg .u64 t; cvta.to.shared.u64 t, %1; cvt.u32.u64 %0, t; }" : "=r"(a) : "l"(p));
    return a;
}

#define LDMATRIX_X4(r0, r1, r2, r3, addr) \
    asm volatile("ldmatrix.sync.aligned.m8n8.x4.shared.b16 {%0,%1,%2,%3}, [%4];" \
        : "=r"(r0), "=r"(r1), "=r"(r2), "=r"(r3) : "r"(addr))

#define MMA_BF16(d, a, b0, b1) \
    asm volatile("mma.sync.aligned.m16n8k16.row.col.f32.bf16.bf16.f32 " \
        "{%0,%1,%2,%3}, {%4,%5,%6,%7}, {%8,%9}, {%0,%1,%2,%3};" \
        : "+f"((d)[0]), "+f"((d)[1]), "+f"((d)[2]), "+f"((d)[3]) \
        : "r"((a)[0]), "r"((a)[1]), "r"((a)[2]), "r"((a)[3]), "r"(b0), "r"(b1))

// bf16 hi/lo split of a float pair -> (hi bf16x2, lo bf16x2); low half = first elem
__device__ __forceinline__ uint2 split_pair(float v0, float v1) {
    uint32 hp, lp;
    asm("cvt.rn.bf16x2.f32 %0, %1, %2;" : "=r"(hp) : "f"(v1), "f"(v0));
    float h0 = __uint_as_float(hp << 16);
    float h1 = __uint_as_float(hp & 0xFFFF0000u);
    float r0 = v0 - h0, r1 = v1 - h1;
    asm("cvt.rn.bf16x2.f32 %0, %1, %2;" : "=r"(lp) : "f"(r1), "f"(r0));
    return make_uint2(hp, lp);
}

// ---------------- CSR build ----------------

__global__ void zero_counts_kernel() {
    int i = blockIdx.x * blockDim.x + threadIdx.x;
    if (i < NN) g_count[i] = 0;
}

__global__ void hist_kernel(const int* __restrict__ dst) {
    int e = blockIdx.x * blockDim.x + threadIdx.x;
    if (e < NE) atomicAdd(&g_count[dst[e]], 1);
}

#define SCAN_T 1024
__global__ void __launch_bounds__(SCAN_T) scan_kernel() {
    __shared__ int s[SCAN_T];
    int tid = threadIdx.x;
    const int CH = (NN + SCAN_T - 1) / SCAN_T;
    int t0 = tid * CH;
    int t1 = t0 + CH; if (t1 > NN) t1 = NN;
    int sum = 0;
    for (int i = t0; i < t1; ++i) sum += g_count[i];
    s[tid] = sum;
    __syncthreads();
    for (int off = 1; off < SCAN_T; off <<= 1) {
        int v = (tid >= off) ? s[tid - off] : 0;
        __syncthreads();
        s[tid] += v;
        __syncthreads();
    }
    int run = s[tid] - sum;
    for (int i = t0; i < t1; ++i) {
        int c = g_count[i];
        g_rowstart[i] = run; run += c;
        g_invdeg[i] = 1.0f / fmaxf((float)c, 1.0f);
        g_cursor[i] = 0;
    }
}

__global__ void fill_kernel(const int* __restrict__ src, const int* __restrict__ dst) {
    int e = blockIdx.x * blockDim.x + threadIdx.x;
    if (e < NE) {
        int d = dst[e];
        int p = atomicAdd(&g_cursor[d], 1);
        g_eidx[g_rowstart[d] + p] = src[e];
    }
}

// ---------------- weight prep: fragment-order B + bias pad ----------------
// For thread lane in an 8-n block nb at k-step ks of chunk:
//   n  = nb*8 + (lane>>2)
//   bq = (lane&3)*2
//   bh0 = bf16hi(W[kb+bq][n]), bf16hi(W[kb+bq+1][n])     (packed, lo half = first)
//   bh1 = same at kb+bq+8 ; bl0/bl1 = bf16lo residuals
// where kb = chunk*128 + ks*16; W = [Wself ; Wneigh] column n (padded to 128).

__device__ __forceinline__ float get_w(int layer, int k, int n,
                                       const float* Ws0, const float* Wn0,
                                       const float* Ws1, const float* Wn1,
                                       const float* Ws2, const float* Wn2) {
    if (layer == 0) return (k < 128) ? Ws0[k * 128 + n] : Wn0[(k - 128) * 128 + n];
    if (layer == 1) return (k < 128) ? Ws1[k * 128 + n] : Wn1[(k - 128) * 128 + n];
    if (n >= 47) return 0.f;
    return (k < 128) ? Ws2[k * 47 + n] : Wn2[(k - 128) * 47 + n];
}

__device__ __forceinline__ void split1(float v, float& hi, float& lo) {
    __nv_bfloat16 hb = __float2bfloat16_rn(v);
    hi = __bfloat162float(hb);
    lo = v - hi;
}

__device__ __forceinline__ uint32 pack_bf16x2(float lo_elem, float hi_elem) {
    uint32 p;
    asm("cvt.rn.bf16x2.f32 %0, %1, %2;" : "=r"(p) : "f"(hi_elem), "f"(lo_elem));
    return p;
}

__global__ void prep_frag_kernel(const float* __restrict__ Ws0, const float* __restrict__ Wn0, const float* __restrict__ b0,
                                 const float* __restrict__ Ws1, const float* __restrict__ Wn1, const float* __restrict__ b1,
                                 const float* __restrict__ Ws2, const float* __restrict__ Wn2, const float* __restrict__ b2) {
    int i = blockIdx.x * blockDim.x + threadIdx.x;   // 0 .. 24575
    if (i < 3 * 2 * 8 * 16 * 32) {
        int lane = i & 31;
        int nb   = (i >> 5) & 15;
        int ks   = (i >> 9) & 7;
        int chunk = (i >> 12) & 1;
        int layer = i >> 13;

        int n  = nb * 8 + (lane >> 2);
        int bq = (lane & 3) * 2;
        int kb = chunk * 128 + ks * 16;

        float h0, l0, h1, l1, h2, l2, h3, l3;
        split1(get_w(layer, kb + bq,     n, Ws0, Wn0, Ws1, Wn1, Ws2, Wn2), h0, l0);
        split1(get_w(layer, kb + bq + 1, n, Ws0, Wn0, Ws1, Wn1, Ws2, Wn2), h1, l1);
        split1(get_w(layer, kb + bq + 8, n, Ws0, Wn0, Ws1, Wn1, Ws2, Wn2), h2, l2);
        split1(get_w(layer, kb + bq + 9, n, Ws0, Wn0, Ws1, Wn1, Ws2, Wn2), h3, l3);

        uint4 f;
        f.x = pack_bf16x2(h0, h1);   // bh0
        f.y = pack_bf16x2(h2, h3);   // bh1
        f.z = pack_bf16x2(l0, l1);   // bl0
        f.w = pack_bf16x2(l2, l3);   // bl1
        g_wfrag[i] = f;
    }
    if (i < 3 * 128) {
        int l = i >> 7, j = i & 127;
        float bv = 0.f;
        if (l == 0) bv = b0[j];
        else if (l == 1) bv = b1[j];
        else if (j < 47) bv = b2[j];
        g_biasp[l][j] = bv;
    }
}

// ---------------- gather: mean neighbor aggregation (CSR, no atomics) ----------------

__global__ void __launch_bounds__(256) gather_kernel(const float* __restrict__ h) {
    int node = (blockIdx.x * blockDim.x + threadIdx.x) >> 5;
    int lane = threadIdx.x & 31;
    if (node >= NN) return;
    int start = g_rowstart[node];
    int len   = g_count[node];
    float4 acc = make_float4(0.f, 0.f, 0.f, 0.f);
    int e = 0;
    for (; e + 4 <= len; e += 4) {
        int s0 = g_eidx[start + e];
        int s1 = g_eidx[start + e + 1];
        int s2 = g_eidx[start + e + 2];
        int s3 = g_eidx[start + e + 3];
        float4 v0 = *(const float4*)(h + (size_t)s0 * FD + lane * 4);
        float4 v1 = *(const float4*)(h + (size_t)s1 * FD + lane * 4);
        float4 v2 = *(const float4*)(h + (size_t)s2 * FD + lane * 4);
        float4 v3 = *(const float4*)(h + (size_t)s3 * FD + lane * 4);
        acc.x += v0.x + v1.x + v2.x + v3.x;
        acc.y += v0.y + v1.y + v2.y + v3.y;
        acc.z += v0.z + v1.z + v2.z + v3.z;
        acc.w += v0.w + v1.w + v2.w + v3.w;
    }
    for (; e < len; ++e) {
        int s0 = g_eidx[start + e];
        float4 v0 = *(const float4*)(h + (size_t)s0 * FD + lane * 4);
        acc.x += v0.x; acc.y += v0.y; acc.z += v0.z; acc.w += v0.w;
    }
    float inv = g_invdeg[node];
    acc.x *= inv; acc.y *= inv; acc.z *= inv; acc.w *= inv;
    *(float4*)(g_hn + (size_t)node * FD + lane * 4) = acc;
}

// ---------------- HMMA bf16-split fused dual GEMM (fragment-ordered B) ----------------
// out[50000, fout] = act( [h | hn] @ Wt^T + bias ), 64-row tiles, K=256 concat.
// Per chunk: A fp32 -> bf16 hi/lo in SMEM (ldmatrix); B fragments via ONE coalesced
// LDG.128 per (ks, nt) from g_wfrag. 3 passes: ahi*bhi + alo*bhi + ahi*blo.
// Block: 8 warps, 2(M) x 4(N); warp tile 32x32; mma m16n8k16.
// smem = 2 * 64 * KPAD * 2 = 34816 (< 48KB, no opt-in).

__global__ void __launch_bounds__(256)
gemm_kernel(const float* __restrict__ h, int layer,
            float* __restrict__ out, int fout, int do_relu)
{
    extern __shared__ unsigned short smem[];
    unsigned short* s_ahi = smem;                 // [64][KPAD]
    unsigned short* s_alo = smem + MTILE * KPAD;

    const int tid = threadIdx.x;
    const int wid = tid >> 5;
    const int lane = tid & 31;
    const int warp_m = wid & 1;     // rows 32*warp_m .. +31
    const int warp_n = wid >> 1;    // cols 32*warp_n .. +31
    const int row0 = blockIdx.x * MTILE;

    const uint32 sa_hi = smem_u32(s_ahi);
    const uint32 sa_lo = smem_u32(s_alo);

    // ldmatrix lane addressing for 16x16 A tiles
    const int lm_l = lane & 7;
    const int lm_g = lane >> 3;
    const int lm_row = ((lm_g & 1) << 3) + lm_l;   // +0/+8 within tile
    const int lm_kof = (lm_g & 2) << 2;            // 0 or 8

    float acc[2][4][4];
#pragma unroll
    for (int mt = 0; mt < 2; ++mt)
#pragma unroll
        for (int nt = 0; nt < 4; ++nt)
#pragma unroll
            for (int c = 0; c < 4; ++c) acc[mt][nt][c] = 0.f;

    for (int chunk = 0; chunk < 2; ++chunk) {
        const float* A = (chunk == 0) ? h : g_hn;
        // --- A fill: 64 rows x 128 k fp32 -> bf16 hi/lo SMEM ---
#pragma unroll
        for (int it = 0; it < 8; ++it) {
            int id = tid + it * 256;       // 0..2047
            int r = id >> 5;               // row in tile (0..63)
            int q = id & 31;               // k-quad
            int row = row0 + r;
            float4 v = make_float4(0.f, 0.f, 0.f, 0.f);
            if (row < NN) v = *(const float4*)(A + (size_t)row * FD + q * 4);
            uint2 p01 = split_pair(v.x, v.y);
            uint2 p23 = split_pair(v.z, v.w);
            uint32* ph = (uint32*)(s_ahi + r * KPAD + q * 4);
            ph[0] = p01.x; ph[1] = p23.x;
            uint32* pl = (uint32*)(s_alo + r * KPAD + q * 4);
            pl[0] = p01.y; pl[1] = p23.y;
        }
        __syncthreads();

        // B fragment base for this (layer, chunk): [ks][nb][lane]
        const uint4* __restrict__ wfrag =
            g_wfrag + ((size_t)(layer * 2 + chunk) << 12);

#pragma unroll
        for (int ks = 0; ks < 8; ++ks) {
            const int k0 = ks * 16;
            // A fragments (hi & lo) for both 16-row tiles
            uint32 ah[2][4], al[2][4];
#pragma unroll
            for (int mt = 0; mt < 2; ++mt) {
                int m = warp_m * 32 + mt * 16 + lm_row;
                uint32 off = (uint32)((m * KPAD + k0 + lm_kof) * 2);
                LDMATRIX_X4(ah[mt][0], ah[mt][1], ah[mt][2], ah[mt][3], sa_hi + off);
                LDMATRIX_X4(al[mt][0], al[mt][1], al[mt][2], al[mt][3], sa_lo + off);
            }
            // B fragments: one coalesced LDG.128 per n-tile
            uint4 bf[4];
#pragma unroll
            for (int nt = 0; nt < 4; ++nt) {
                int nb = warp_n * 4 + nt;
                bf[nt] = __ldg(&wfrag[((ks * 16 + nb) << 5) + lane]);
            }
#pragma unroll
            for (int nt = 0; nt < 4; ++nt) {
#pragma unroll
                for (int mt = 0; mt < 2; ++mt) {
                    MMA_BF16(acc[mt][nt], ah[mt], bf[nt].x, bf[nt].y);   // hi*hi
                    MMA_BF16(acc[mt][nt], al[mt], bf[nt].x, bf[nt].y);   // lo*hi
                    MMA_BF16(acc[mt][nt], ah[mt], bf[nt].z, bf[nt].w);   // hi*lo
                }
            }
        }
        __syncthreads();
    }

    // --- epilogue: bias + relu + store ---
    const float* bias = g_biasp[layer];
#pragma unroll
    for (int mt = 0; mt < 2; ++mt) {
        int r_a = row0 + warp_m * 32 + mt * 16 + (lane >> 2);
        int r_b = r_a + 8;
#pragma unroll
        for (int nt = 0; nt < 4; ++nt) {
            int j0 = warp_n * 32 + nt * 8 + (lane & 3) * 2;
            float b0v = bias[j0], b1v = bias[j0 + 1];
            float v0 = acc[mt][nt][0] + b0v;
            float v1 = acc[mt][nt][1] + b1v;
            float v2 = acc[mt][nt][2] + b0v;
            float v3 = acc[mt][nt][3] + b1v;
            if (do_relu) {
                v0 = fmaxf(v0, 0.f); v1 = fmaxf(v1, 0.f);
                v2 = fmaxf(v2, 0.f); v3 = fmaxf(v3, 0.f);
            }
            if (r_a < NN) {
                if (j0 < fout)     out[(size_t)r_a * fout + j0]     = v0;
                if (j0 + 1 < fout) out[(size_t)r_a * fout + j0 + 1] = v1;
            }
            if (r_b < NN) {
                if (j0 < fout)     out[(size_t)r_b * fout + j0]     = v2;
                if (j0 + 1 < fout) out[(size_t)r_b * fout + j0 + 1] = v3;
            }
        }
    }
}

// ---------------- launch ----------------

extern "C" void kernel_launch(void* const* d_in, const int* in_sizes, int n_in,
                              void* d_out, int out_size) {
    const float* x   = (const float*)d_in[0];
    const int*   src = (const int*)d_in[1];
    const int*   dst = (const int*)d_in[2];
    const float* Ws0 = (const float*)d_in[3];
    const float* Wn0 = (const float*)d_in[4];
    const float* b0  = (const float*)d_in[5];
    const float* Ws1 = (const float*)d_in[6];
    const float* Wn1 = (const float*)d_in[7];
    const float* b1  = (const float*)d_in[8];
    const float* Ws2 = (const float*)d_in[9];
    const float* Wn2 = (const float*)d_in[10];
    const float* b2  = (const float*)d_in[11];
    float* out = (float*)d_out;

    float *h1, *h2;
    cudaGetSymbolAddress((void**)&h1, g_h1);
    cudaGetSymbolAddress((void**)&h2, g_h2);

    const int smem_bytes = 2 * MTILE * KPAD * 2;   // 34816 < 48KB

    const int ZB = 256;
    const int node_grid   = (NN + ZB - 1) / ZB;
    const int edge_grid   = (NE + ZB - 1) / ZB;
    const int gather_grid = (NN * 32 + ZB - 1) / ZB;
    const int prep_grid   = (3 * 2 * 8 * 16 * 32 + ZB - 1) / ZB;

    // CSR build + weight prep
    zero_counts_kernel<<<node_grid, ZB>>>();
    hist_kernel<<<edge_grid, ZB>>>(dst);
    scan_kernel<<<1, SCAN_T>>>();
    fill_kernel<<<edge_grid, ZB>>>(src, dst);
    prep_frag_kernel<<<prep_grid, ZB>>>(Ws0, Wn0, b0, Ws1, Wn1, b1, Ws2, Wn2, b2);

    // layer 0: x -> h1 (relu)
    gather_kernel<<<gather_grid, ZB>>>(x);
    gemm_kernel<<<NTILES, 256, smem_bytes>>>(x, 0, h1, 128, 1);

    // layer 1: h1 -> h2 (relu)
    gather_kernel<<<gather_grid, ZB>>>(h1);
    gemm_kernel<<<NTILES, 256, smem_bytes>>>(h1, 1, h2, 128, 1);

    // layer 2: h2 -> out (no relu, fout=47)
    gather_kernel<<<gather_grid, ZB>>>(h2);
    gemm_kernel<<<NTILES, 256, smem_bytes>>>(h2, 2, out, 47, 0);
}